// round 15
// baseline (speedup 1.0000x reference)
#include <cuda_runtime.h>
#include <cuda_bf16.h>
#include <cuda_fp16.h>
#include <math.h>
#include <stdint.h>

#define NTOK   131072
#define NBALLS 1024

// ---------------- scratch (device globals; allocation forbidden) ------------
__device__ float g_qkv[NTOK * 768];
__device__ float g_x2 [NTOK * 256];
__device__ __nv_bfloat16 g_hh[NTOK * 256], g_hl[NTOK * 256];   // norm_pe out (qkv A)
__device__ __nv_bfloat16 g_wqh[196608],    g_wql[196608];      // qkv W split
__device__ __half g_a16[NTOK * 256];     // attention out (fp16)
__device__ __half g_h16[NTOK * 256];     // rmsnorm2 out (fp16)
__device__ __half g_g16[NTOK * 1024];    // gated MLP hidden (fp16)
__device__ __half g_w16[851968];         // proj | w1 | w2 | w3 (fp16)
__device__ __half g_dist[NBALLS * 16384];// per-ball pairwise distances (fp16)

// ---------------- helpers ----------------
__device__ __forceinline__ uint32_t smem_u32(const void* p) {
    return (uint32_t)__cvta_generic_to_shared(p);
}
__device__ __forceinline__ void ldsm4(uint32_t* d, uint32_t addr) {
    asm volatile("ldmatrix.sync.aligned.m8n8.x4.shared.b16 {%0,%1,%2,%3}, [%4];"
        : "=r"(d[0]), "=r"(d[1]), "=r"(d[2]), "=r"(d[3]) : "r"(addr));
}
__device__ __forceinline__ void mma_bf(float* c, const uint32_t* a,
                                       uint32_t b0, uint32_t b1) {
    asm volatile(
        "mma.sync.aligned.m16n8k16.row.col.f32.bf16.bf16.f32 "
        "{%0,%1,%2,%3}, {%4,%5,%6,%7}, {%8,%9}, {%0,%1,%2,%3};"
        : "+f"(c[0]), "+f"(c[1]), "+f"(c[2]), "+f"(c[3])
        : "r"(a[0]), "r"(a[1]), "r"(a[2]), "r"(a[3]), "r"(b0), "r"(b1));
}
__device__ __forceinline__ void mma_h(float* c, const uint32_t* a,
                                      uint32_t b0, uint32_t b1) {
    asm volatile(
        "mma.sync.aligned.m16n8k16.row.col.f32.f16.f16.f32 "
        "{%0,%1,%2,%3}, {%4,%5,%6,%7}, {%8,%9}, {%0,%1,%2,%3};"
        : "+f"(c[0]), "+f"(c[1]), "+f"(c[2]), "+f"(c[3])
        : "r"(a[0]), "r"(a[1]), "r"(a[2]), "r"(a[3]), "r"(b0), "r"(b1));
}
__device__ __forceinline__ void cpa16(uint32_t dst, const void* src) {
    asm volatile("cp.async.ca.shared.global [%0], [%1], 16;"
        :: "r"(dst), "l"(src) : "memory");
}
#define CPA_COMMIT() asm volatile("cp.async.commit_group;" ::: "memory")
#define CPA_WAIT1()  asm volatile("cp.async.wait_group 1;"  ::: "memory")
#define CPA_WAIT0()  asm volatile("cp.async.wait_group 0;"  ::: "memory")

__device__ __forceinline__ void split_store2(
    __nv_bfloat16* H, __nv_bfloat16* L, size_t off, float a, float b)
{
    __nv_bfloat16 ha = __float2bfloat16(a), hb = __float2bfloat16(b);
    __nv_bfloat162 hv, lv;
    hv.x = ha; hv.y = hb;
    lv.x = __float2bfloat16(a - __bfloat162float(ha));
    lv.y = __float2bfloat16(b - __bfloat162float(hb));
    *(__nv_bfloat162*)(H + off) = hv;
    *(__nv_bfloat162*)(L + off) = lv;
}
__device__ __forceinline__ void split_store4(
    __nv_bfloat16* H, __nv_bfloat16* L, size_t off,
    float a, float b, float c, float d)
{
    split_store2(H, L, off,     a, b);
    split_store2(H, L, off + 2, c, d);
}

// ---------------- weight prep ----------------
__global__ void __launch_bounds__(256) split_kernel(
    const float* __restrict__ w, __nv_bfloat16* __restrict__ h,
    __nv_bfloat16* __restrict__ l, int n4)
{
    int i = blockIdx.x * 256 + threadIdx.x;
    if (i >= n4) return;
    float4 v = ((const float4*)w)[i];
    split_store4(h, l, (size_t)i * 4, v.x, v.y, v.z, v.w);
}
__global__ void __launch_bounds__(256) hconv_kernel(
    const float* __restrict__ w, __half* __restrict__ o, int n4)
{
    int i = blockIdx.x * 256 + threadIdx.x;
    if (i >= n4) return;
    float4 v = ((const float4*)w)[i];
    *(__half2*)(o + (size_t)i * 4)     = __floats2half2_rn(v.x, v.y);
    *(__half2*)(o + (size_t)i * 4 + 2) = __floats2half2_rn(v.z, v.w);
}

// ---------------- K0: per-ball pairwise distance (fp16) ---------------------
__global__ void __launch_bounds__(128) dist_kernel(
    const float* __restrict__ pos, __half* __restrict__ dout)
{
    __shared__ float px[128], py[128], pz[128];
    const int ball = blockIdx.x, t = threadIdx.x;
    float ax = pos[(size_t)ball * 384 + t*3];
    float ay = pos[(size_t)ball * 384 + t*3 + 1];
    float az = pos[(size_t)ball * 384 + t*3 + 2];
    px[t] = ax; py[t] = ay; pz[t] = az;
    __syncthreads();
    size_t base = (size_t)ball * 16384;
    #pragma unroll 4
    for (int r = 0; r < 128; r++) {
        float dx = px[r]-ax, dy = py[r]-ay, dz = pz[r]-az;
        dout[base + r*128 + t] = __float2half(sqrtf(dx*dx + dy*dy + dz*dz));
    }
}

// ---------------- K1: rmsnorm1 + rel-pos embedding -> bf16 hi/lo ------------
__global__ void __launch_bounds__(256) norm_pe_kernel(
    const float* __restrict__ x, const float* __restrict__ pos,
    const float* __restrict__ nw, const float* __restrict__ pew,
    const float* __restrict__ peb,
    __nv_bfloat16* __restrict__ oh, __nv_bfloat16* __restrict__ ol)
{
    __shared__ float s_pe[768], s_peb[256], s_nw[256], s_pos[384], s_mean[3];
    const int ball = blockIdx.x, tid = threadIdx.x;
    for (int i = tid; i < 768; i += 256) s_pe[i] = pew[i];
    s_peb[tid] = peb[tid];
    s_nw[tid]  = nw[tid];
    for (int i = tid; i < 384; i += 256) s_pos[i] = pos[(size_t)ball * 384 + i];
    __syncthreads();
    if (tid < 3) {
        float s = 0.f;
        for (int t = 0; t < 128; t++) s += s_pos[t * 3 + tid];
        s_mean[tid] = s * (1.f / 128.f);
    }
    __syncthreads();

    const int warp = tid >> 5, lane = tid & 31;
    for (int tok = warp; tok < 128; tok += 8) {
        size_t row = (size_t)ball * 128 + tok;
        const float4* xr = (const float4*)(x + row * 256);
        float4 v0 = xr[lane], v1 = xr[lane + 32];
        float ss = v0.x*v0.x + v0.y*v0.y + v0.z*v0.z + v0.w*v0.w
                 + v1.x*v1.x + v1.y*v1.y + v1.z*v1.z + v1.w*v1.w;
        #pragma unroll
        for (int o = 16; o; o >>= 1) ss += __shfl_xor_sync(0xffffffffu, ss, o);
        float sc = rsqrtf(ss * (1.f / 256.f) + 1e-6f);
        float rx = s_pos[tok*3+0] - s_mean[0];
        float ry = s_pos[tok*3+1] - s_mean[1];
        float rz = s_pos[tok*3+2] - s_mean[2];
        float vin[8] = {v0.x,v0.y,v0.z,v0.w,v1.x,v1.y,v1.z,v1.w};
        float vo[8];
        #pragma unroll
        for (int j = 0; j < 8; j++) {
            int d = (j < 4) ? lane*4 + j : 128 + lane*4 + (j-4);
            vo[j] = vin[j] * sc * s_nw[d]
                  + rx * s_pe[d*3] + ry * s_pe[d*3+1] + rz * s_pe[d*3+2] + s_peb[d];
        }
        split_store4(oh, ol, row*256 + lane*4,       vo[0], vo[1], vo[2], vo[3]);
        split_store4(oh, ol, row*256 + 128 + lane*4, vo[4], vo[5], vo[6], vo[7]);
    }
}

// ---------- GEMM A: 3-term bf16 split (qkv only), 2-stage cp.async ----------
__global__ void __launch_bounds__(256) gemm_split3_kernel(
    const __nv_bfloat16* __restrict__ Ah, const __nv_bfloat16* __restrict__ Al,
    const __nv_bfloat16* __restrict__ Bh, const __nv_bfloat16* __restrict__ Bl,
    const float* __restrict__ bias, float* __restrict__ outF, int Nn, int K)
{
    constexpr int OA0 = 0, OA1 = 10240, OB0 = 20480;
    constexpr int BT  = 10240, CS = 40960;
    extern __shared__ char sm[];
    const uint32_t sb = smem_u32(sm);
    const int tid = threadIdx.x, lane = tid & 31, wid = tid >> 5;
    const int wm = wid >> 1, wn = wid & 1;
    const int bn = blockIdx.x * 128, bm = blockIdx.y * 128;

    float acc[2][8][4];
    #pragma unroll
    for (int mi = 0; mi < 2; mi++)
        #pragma unroll
        for (int ni = 0; ni < 8; ni++)
            #pragma unroll
            for (int q = 0; q < 4; q++) acc[mi][ni][q] = 0.f;

    const int NC = K >> 5;
    auto issue = [&](int c) {
        const int k0 = c << 5;
        const uint32_t bb = sb + (c & 1) * CS;
        #pragma unroll
        for (int i = 0; i < 2; i++) {
            int u = tid + i * 256, r = u >> 2, s = (u & 3) * 8;
            uint32_t so = (uint32_t)r * 80 + s * 2;
            cpa16(bb + OA0 + so, Ah + (size_t)(bm + r) * K + k0 + s);
            cpa16(bb + OA1 + so, Al + (size_t)(bm + r) * K + k0 + s);
            size_t go = (size_t)(bn + r) * K + k0 + s;
            cpa16(bb + OB0 +    so, Bh + go);
            cpa16(bb + OB0 + BT + so, Bl + go);
        }
        CPA_COMMIT();
    };

    issue(0);
    for (int c = 0; c < NC; c++) {
        if (c + 1 < NC) { issue(c + 1); CPA_WAIT1(); }
        else            { CPA_WAIT0(); }
        __syncthreads();
        const uint32_t bb = sb + (c & 1) * CS;
        #pragma unroll
        for (int ks = 0; ks < 32; ks += 16) {
            uint32_t ah[2][4], al[2][4];
            const int ar = lane & 15, ac = ks + (lane >> 4) * 8;
            #pragma unroll
            for (int mi = 0; mi < 2; mi++) {
                uint32_t off = (uint32_t)(wm*32 + mi*16 + ar) * 80 + ac * 2;
                ldsm4(ah[mi], bb + OA0 + off);
                ldsm4(al[mi], bb + OA1 + off);
            }
            const int br = (lane & 7) + ((lane & 16) ? 8 : 0);
            const int bc = ks + ((lane & 8) ? 8 : 0);
            uint32_t bh[4][4], bl[4][4];
            #pragma unroll
            for (int np = 0; np < 4; np++) {
                uint32_t off = (uint32_t)(wn*64 + np*16 + br) * 80 + bc * 2;
                ldsm4(bh[np], bb + OB0 + off);
                ldsm4(bl[np], bb + OB0 + BT + off);
            }
            #pragma unroll
            for (int mi = 0; mi < 2; mi++)
                #pragma unroll
                for (int ni = 0; ni < 8; ni++) {
                    int np = ni >> 1, hb = (ni & 1) * 2;
                    mma_bf(acc[mi][ni], ah[mi], bh[np][hb], bh[np][hb+1]);
                    mma_bf(acc[mi][ni], ah[mi], bl[np][hb], bl[np][hb+1]);
                    mma_bf(acc[mi][ni], al[mi], bh[np][hb], bh[np][hb+1]);
                }
        }
        __syncthreads();
    }

    const int rb = bm + wm*32 + (lane >> 2);
    const int cb = bn + wn*64 + (lane & 3)*2;
    #pragma unroll
    for (int mi = 0; mi < 2; mi++)
        #pragma unroll
        for (int ni = 0; ni < 8; ni++) {
            const int col = cb + ni*8;
            float bx = __ldg(&bias[col]), by = __ldg(&bias[col+1]);
            #pragma unroll
            for (int hr = 0; hr < 2; hr++) {
                size_t o = (size_t)(rb + mi*16 + hr*8) * Nn + col;
                *(float2*)&outF[o] = make_float2(acc[mi][ni][hr*2] + bx,
                                                 acc[mi][ni][hr*2+1] + by);
            }
        }
}

// ---------- GEMM B: single-pass fp16 (proj / w3 / mlp-gate) -----------------
template<bool RES, bool GATE>
__global__ void __launch_bounds__(256) gemm_h_kernel(
    const __half* __restrict__ A,  const __half* __restrict__ B1,
    const __half* __restrict__ B2, const float* __restrict__ bias,
    const float* __restrict__ bias2, const float* __restrict__ res,
    float* __restrict__ outF, __half* __restrict__ outG, int Nn, int K)
{
    constexpr int BN  = GATE ? 64 : 128;
    constexpr int NPW = BN / 32, NI = BN / 16;
    constexpr int OA = 0, OB = 10240;
    constexpr int BT = BN * 80;
    constexpr int CS = 20480;
    extern __shared__ char sm[];
    const uint32_t sb = smem_u32(sm);
    const int tid = threadIdx.x, lane = tid & 31, wid = tid >> 5;
    const int wm = wid >> 1, wn = wid & 1;
    const int bn = blockIdx.x * BN, bm = blockIdx.y * 128;

    float acc [2][NI][4];
    float accV[2][NI][4];
    #pragma unroll
    for (int mi = 0; mi < 2; mi++)
        #pragma unroll
        for (int ni = 0; ni < NI; ni++)
            #pragma unroll
            for (int q = 0; q < 4; q++) {
                acc[mi][ni][q] = 0.f;
                if (GATE) accV[mi][ni][q] = 0.f;
            }

    const int NC = K >> 5;
    auto issue = [&](int c) {
        const int k0 = c << 5;
        const uint32_t bb = sb + (c & 1) * CS;
        #pragma unroll
        for (int i = 0; i < 2; i++) {
            int u = tid + i * 256, r = u >> 2, s = (u & 3) * 8;
            cpa16(bb + OA + (uint32_t)r * 80 + s * 2,
                  A + (size_t)(bm + r) * K + k0 + s);
        }
        if (GATE) {
            int r = tid >> 2, s = (tid & 3) * 8;
            uint32_t so = (uint32_t)r * 80 + s * 2;
            size_t go = (size_t)(bn + r) * K + k0 + s;
            cpa16(bb + OB +    so, B1 + go);
            cpa16(bb + OB + BT + so, B2 + go);
        } else {
            #pragma unroll
            for (int i = 0; i < 2; i++) {
                int u = tid + i * 256, r = u >> 2, s = (u & 3) * 8;
                cpa16(bb + OB + (uint32_t)r * 80 + s * 2,
                      B1 + (size_t)(bn + r) * K + k0 + s);
            }
        }
        CPA_COMMIT();
    };

    issue(0);
    for (int c = 0; c < NC; c++) {
        if (c + 1 < NC) { issue(c + 1); CPA_WAIT1(); }
        else            { CPA_WAIT0(); }
        __syncthreads();
        const uint32_t bb = sb + (c & 1) * CS;
        #pragma unroll
        for (int ks = 0; ks < 32; ks += 16) {
            uint32_t ah[2][4];
            const int ar = lane & 15, ac = ks + (lane >> 4) * 8;
            #pragma unroll
            for (int mi = 0; mi < 2; mi++)
                ldsm4(ah[mi], bb + OA + (uint32_t)(wm*32 + mi*16 + ar) * 80 + ac * 2);
            const int br = (lane & 7) + ((lane & 16) ? 8 : 0);
            const int bc = ks + ((lane & 8) ? 8 : 0);
            uint32_t bh[NPW][4], b2[NPW][4];
            #pragma unroll
            for (int np = 0; np < NPW; np++) {
                uint32_t off = (uint32_t)(wn*(BN/2) + np*16 + br) * 80 + bc * 2;
                ldsm4(bh[np], bb + OB + off);
                if (GATE) ldsm4(b2[np], bb + OB + BT + off);
            }
            #pragma unroll
            for (int mi = 0; mi < 2; mi++)
                #pragma unroll
                for (int ni = 0; ni < NI; ni++) {
                    int np = ni >> 1, hb = (ni & 1) * 2;
                    mma_h(acc[mi][ni], ah[mi], bh[np][hb], bh[np][hb+1]);
                    if (GATE) mma_h(accV[mi][ni], ah[mi], b2[np][hb], b2[np][hb+1]);
                }
        }
        __syncthreads();
    }

    const int rb = bm + wm*32 + (lane >> 2);
    const int cb = bn + wn*(BN/2) + (lane & 3)*2;
    #pragma unroll
    for (int mi = 0; mi < 2; mi++)
        #pragma unroll
        for (int ni = 0; ni < NI; ni++) {
            const int col = cb + ni*8;
            if (GATE) {
                #pragma unroll
                for (int hr = 0; hr < 2; hr++) {
                    size_t o = (size_t)(rb + mi*16 + hr*8) * 1024 + col;
                    float g0 = acc [mi][ni][hr*2]   + __ldg(&bias [col]);
                    float g1 = acc [mi][ni][hr*2+1] + __ldg(&bias [col+1]);
                    float v0 = accV[mi][ni][hr*2]   + __ldg(&bias2[col]);
                    float v1 = accV[mi][ni][hr*2+1] + __ldg(&bias2[col+1]);
                    float r0 = (g0 / (1.f + __expf(-g0))) * v0;
                    float r1 = (g1 / (1.f + __expf(-g1))) * v1;
                    *(__half2*)&outG[o] = __floats2half2_rn(r0, r1);
                }
            } else {
                float bx = __ldg(&bias[col]), by = __ldg(&bias[col+1]);
                #pragma unroll
                for (int hr = 0; hr < 2; hr++) {
                    size_t o = (size_t)(rb + mi*16 + hr*8) * Nn + col;
                    float2 v = make_float2(acc[mi][ni][hr*2] + bx,
                                           acc[mi][ni][hr*2+1] + by);
                    if (RES) {
                        float2 rr = *(const float2*)&res[o];
                        v.x += rr.x; v.y += rr.y;
                    }
                    *(float2*)&outF[o] = v;
                }
            }
        }
}

// ---------------- K3: attention, block per (ball, head), precomputed d ------
__global__ void __launch_bounds__(128) attn_kernel(
    const float* __restrict__ qkv, const __half* __restrict__ dist,
    const float* __restrict__ sigma, __half* __restrict__ oh)
{
    extern __shared__ float smf[];
    float*  qsm    = smf;                        // [128][36]
    float*  ksm    = qsm + 4608;
    float*  vsm    = ksm + 4608;
    __half* dsm    = (__half*)(smf + 13824);     // [128][136]
    float*  probsm = smf + 13824 + 8704;         // 4 warps x [8][132]

    const int ball = blockIdx.x, h = blockIdx.y;
    const int tid = threadIdx.x;
    const size_t base = (size_t)ball * 128 * 768 + (size_t)h * 96;

    for (int idx = tid; idx < 128 * 96; idx += 128) {
        int tok = idx / 96, c = idx - tok * 96;
        int e = c / 3, wch = c - e * 3;
        float v = qkv[base + (size_t)tok * 768 + c];
        if (wch == 0)      qsm[tok * 36 + e] = v;
        else if (wch == 1) ksm[tok * 36 + e] = v;
        else               vsm[tok * 36 + e] = v;
    }
    {   // load d tile: 16384 fp16 -> [128][136]
        const __half* dg = dist + (size_t)ball * 16384;
        for (int i = tid; i < 2048; i += 128) {
            int r = i >> 4, c = i & 15;
            *(uint4*)((char*)dsm + r * 272 + c * 16) =
                *(const uint4*)(dg + r * 128 + c * 8);
        }
    }
    __syncthreads();

    const float sig = sigma[h];
    const float inv = 0.17677669529663687f;   // 1/sqrt(32)
    const int warp = tid >> 5, lane = tid & 31;
    float* prob = probsm + warp * (8 * 132);
    const int qbase = warp * 32;

    for (int qc = 0; qc < 4; qc++) {
        const int qs = qbase + qc * 8;

        float acc[8][4];
        #pragma unroll
        for (int j = 0; j < 8; j++)
            #pragma unroll
            for (int t = 0; t < 4; t++) acc[j][t] = 0.f;

        #pragma unroll
        for (int e4 = 0; e4 < 8; e4++) {
            float4 kv[4];
            #pragma unroll
            for (int t = 0; t < 4; t++)
                kv[t] = *(const float4*)&ksm[(lane * 4 + t) * 36 + e4 * 4];
            #pragma unroll
            for (int j = 0; j < 8; j++) {
                float4 qv = *(const float4*)&qsm[(qs + j) * 36 + e4 * 4];
                #pragma unroll
                for (int t = 0; t < 4; t++)
                    acc[j][t] += qv.x*kv[t].x + qv.y*kv[t].y + qv.z*kv[t].z + qv.w*kv[t].w;
            }
        }

        #pragma unroll
        for (int j = 0; j < 8; j++) {
            const __half* drow = dsm + (qs + j) * 136 + lane * 4;
            float2 f01 = __half22float2(*(const __half2*)drow);
            float2 f23 = __half22float2(*(const __half2*)(drow + 2));
            float s[4];
            s[0] = acc[j][0] * inv + sig * f01.x;
            s[1] = acc[j][1] * inv + sig * f01.y;
            s[2] = acc[j][2] * inv + sig * f23.x;
            s[3] = acc[j][3] * inv + sig * f23.y;
            float m = fmaxf(fmaxf(s[0], s[1]), fmaxf(s[2], s[3]));
            #pragma unroll
            for (int o = 16; o; o >>= 1) m = fmaxf(m, __shfl_xor_sync(0xffffffffu, m, o));
            float e0 = __expf(s[0]-m), e1 = __expf(s[1]-m);
            float e2 = __expf(s[2]-m), e3 = __expf(s[3]-m);
            float sum = e0 + e1 + e2 + e3;
            #pragma unroll
            for (int o = 16; o; o >>= 1) sum += __shfl_xor_sync(0xffffffffu, sum, o);
            float r = 1.f / sum;
            *(float4*)&prob[j * 132 + lane * 4] = make_float4(e0*r, e1*r, e2*r, e3*r);
        }
        __syncwarp();

        float av[8] = {0,0,0,0,0,0,0,0};
        #pragma unroll 4
        for (int k4 = 0; k4 < 32; k4++) {
            float vv0 = vsm[(k4*4+0)*36 + lane];
            float vv1 = vsm[(k4*4+1)*36 + lane];
            float vv2 = vsm[(k4*4+2)*36 + lane];
            float vv3 = vsm[(k4*4+3)*36 + lane];
            #pragma unroll
            for (int j = 0; j < 8; j++) {
                float4 pv = *(const float4*)&prob[j * 132 + k4 * 4];
                av[j] += pv.x*vv0 + pv.y*vv1 + pv.z*vv2 + pv.w*vv3;
            }
        }
        #pragma unroll
        for (int j = 0; j < 8; j++) {
            size_t o = ((size_t)ball * 128 + qs + j) * 256 + h * 32 + lane;
            oh[o] = __float2half(av[j]);
        }
        __syncwarp();
    }
}

// ---------------- K5: rmsnorm -> fp16 ----------------
__global__ void __launch_bounds__(256) rmsnorm_kernel(
    const float* __restrict__ x, const float* __restrict__ w,
    __half* __restrict__ oh)
{
    const int warp = threadIdx.x >> 5, lane = threadIdx.x & 31;
    size_t row = (size_t)blockIdx.x * 8 + warp;
    const float4* xr = (const float4*)(x + row * 256);
    float4 v0 = xr[lane], v1 = xr[lane + 32];
    float ss = v0.x*v0.x + v0.y*v0.y + v0.z*v0.z + v0.w*v0.w
             + v1.x*v1.x + v1.y*v1.y + v1.z*v1.z + v1.w*v1.w;
    #pragma unroll
    for (int o = 16; o; o >>= 1) ss += __shfl_xor_sync(0xffffffffu, ss, o);
    float sc = rsqrtf(ss * (1.f / 256.f) + 1e-6f);
    const float4* w4 = (const float4*)w;
    float4 w0 = w4[lane], w1 = w4[lane + 32];
    size_t o0 = row*256 + lane*4, o1 = row*256 + 128 + lane*4;
    *(__half2*)(oh + o0)     = __floats2half2_rn(v0.x*sc*w0.x, v0.y*sc*w0.y);
    *(__half2*)(oh + o0 + 2) = __floats2half2_rn(v0.z*sc*w0.z, v0.w*sc*w0.w);
    *(__half2*)(oh + o1)     = __floats2half2_rn(v1.x*sc*w1.x, v1.y*sc*w1.y);
    *(__half2*)(oh + o1 + 2) = __floats2half2_rn(v1.z*sc*w1.z, v1.w*sc*w1.w);
}

// ---------------------------------------------------------------------------
extern "C" void kernel_launch(void* const* d_in, const int* in_sizes, int n_in,
                              void* d_out, int out_size)
{
    const float* x      = (const float*)d_in[0];
    const float* pos    = (const float*)d_in[1];
    const float* qkv_w  = (const float*)d_in[3];
    const float* qkv_b  = (const float*)d_in[4];
    const float* proj_w = (const float*)d_in[5];
    const float* proj_b = (const float*)d_in[6];
    const float* pe_w   = (const float*)d_in[7];
    const float* pe_b   = (const float*)d_in[8];
    const float* sigma  = (const float*)d_in[9];
    const float* n1w    = (const float*)d_in[10];
    const float* n2w    = (const float*)d_in[11];
    const float* w1w    = (const float*)d_in[12];
    const float* w1b    = (const float*)d_in[13];
    const float* w2w    = (const float*)d_in[14];
    const float* w2b    = (const float*)d_in[15];
    const float* w3w    = (const float*)d_in[16];
    const float* w3b    = (const float*)d_in[17];
    float* out = (float*)d_out;

    float *p_qkv, *p_x2;
    __nv_bfloat16 *p_hh, *p_hl, *p_wqh, *p_wql;
    __half *p_a16, *p_h16, *p_g16, *p_w16, *p_dist;
    cudaGetSymbolAddress((void**)&p_qkv, g_qkv);
    cudaGetSymbolAddress((void**)&p_x2,  g_x2);
    cudaGetSymbolAddress((void**)&p_hh,  g_hh);
    cudaGetSymbolAddress((void**)&p_hl,  g_hl);
    cudaGetSymbolAddress((void**)&p_wqh, g_wqh);
    cudaGetSymbolAddress((void**)&p_wql, g_wql);
    cudaGetSymbolAddress((void**)&p_a16, g_a16);
    cudaGetSymbolAddress((void**)&p_h16, g_h16);
    cudaGetSymbolAddress((void**)&p_g16, g_g16);
    cudaGetSymbolAddress((void**)&p_w16, g_w16);
    cudaGetSymbolAddress((void**)&p_dist, g_dist);

    const int O_PROJ = 0, O_W1 = 65536, O_W2 = 327680, O_W3 = 589824;

    const int ATTN_SMEM = (13824 + 8704 + 4224) * 4;   // 107008 B
    cudaFuncSetAttribute(attn_kernel,
                         cudaFuncAttributeMaxDynamicSharedMemorySize, ATTN_SMEM);
    const int GSM  = 81920;   // split3: 2 x 40960
    const int GSMH = 40960;   // fp16:  2 x 20480
    cudaFuncSetAttribute(gemm_split3_kernel, cudaFuncAttributeMaxDynamicSharedMemorySize, GSM);
    cudaFuncSetAttribute(gemm_h_kernel<true,false>,  cudaFuncAttributeMaxDynamicSharedMemorySize, GSMH);
    cudaFuncSetAttribute(gemm_h_kernel<false,true>,  cudaFuncAttributeMaxDynamicSharedMemorySize, GSMH);

    // 0) weight prep + distance precompute
    split_kernel<<<(196608/4+255)/256, 256>>>(qkv_w, p_wqh, p_wql, 196608/4);
    hconv_kernel<<<( 65536/4+255)/256, 256>>>(proj_w, p_w16+O_PROJ,  65536/4);
    hconv_kernel<<<(262144/4+255)/256, 256>>>(w1w,    p_w16+O_W1,   262144/4);
    hconv_kernel<<<(262144/4+255)/256, 256>>>(w2w,    p_w16+O_W2,   262144/4);
    hconv_kernel<<<(262144/4+255)/256, 256>>>(w3w,    p_w16+O_W3,   262144/4);
    dist_kernel<<<NBALLS, 128>>>(pos, p_dist);

    // 1) h = rmsnorm1(x) + pe   (bf16 hi/lo)
    norm_pe_kernel<<<NBALLS, 256>>>(x, pos, n1w, pe_w, pe_b, p_hh, p_hl);

    // 2) qkv = h @ qkv_w^T + b   (3-term bf16 split, fp32 out, stride 768)
    gemm_split3_kernel<<<dim3(6, NTOK/128), 256, GSM>>>(
        p_hh, p_hl, p_wqh, p_wql, qkv_b, p_qkv, 768, 256);

    // 3) att = ball attention    (fp16 out)
    attn_kernel<<<dim3(NBALLS, 8), 128, ATTN_SMEM>>>(p_qkv, p_dist, sigma, p_a16);

    // 4) x2 = att @ proj^T + b + x   (fp16 single-pass)
    gemm_h_kernel<true,false><<<dim3(2, NTOK/128), 256, GSMH>>>(
        p_a16, p_w16+O_PROJ, nullptr, proj_b, nullptr, x, p_x2, nullptr, 256, 256);

    // 5) h = rmsnorm2(x2)        (fp16)
    rmsnorm_kernel<<<NTOK/8, 256>>>(p_x2, n2w, p_h16);

    // 6) g = silu(h@w1^T+b1)*(h@w2^T+b2)   (fp16, stride 1024)
    gemm_h_kernel<false,true><<<dim3(16, NTOK/128), 256, GSMH>>>(
        p_h16, p_w16+O_W1, p_w16+O_W2, w1b, w2b, nullptr, nullptr, p_g16, 1024, 256);

    // 7) out = g @ w3^T + b3 + x2   (fp16 single-pass)
    gemm_h_kernel<true,false><<<dim3(2, NTOK/128), 256, GSMH>>>(
        p_g16, p_w16+O_W3, nullptr, w3b, nullptr, p_x2, out, nullptr, 256, 1024);
}

// round 17
// speedup vs baseline: 1.2587x; 1.2587x over previous
#include <cuda_runtime.h>
#include <cuda_bf16.h>
#include <cuda_fp16.h>
#include <math.h>
#include <stdint.h>

#define NTOK   131072
#define NBALLS 1024

// ---------------- scratch (device globals; allocation forbidden) ------------
__device__ float g_qkv[NTOK * 768];
__device__ float g_x2 [NTOK * 256];
__device__ __nv_bfloat16 g_hh[NTOK * 256], g_hl[NTOK * 256];   // norm_pe out (qkv A)
__device__ __nv_bfloat16 g_wqh[196608],    g_wql[196608];      // qkv W split
__device__ __half g_a16[NTOK * 256];     // attention out (fp16)
__device__ __half g_h16[NTOK * 256];     // rmsnorm2 out (fp16)
__device__ __half g_g16[NTOK * 1024];    // gated MLP hidden (fp16)
__device__ __half g_w16[851968];         // proj | w1 | w2 | w3 (fp16)

// ---------------- helpers ----------------
__device__ __forceinline__ uint32_t smem_u32(const void* p) {
    return (uint32_t)__cvta_generic_to_shared(p);
}
__device__ __forceinline__ void ldsm4(uint32_t* d, uint32_t addr) {
    asm volatile("ldmatrix.sync.aligned.m8n8.x4.shared.b16 {%0,%1,%2,%3}, [%4];"
        : "=r"(d[0]), "=r"(d[1]), "=r"(d[2]), "=r"(d[3]) : "r"(addr));
}
__device__ __forceinline__ void mma_bf(float* c, const uint32_t* a,
                                       uint32_t b0, uint32_t b1) {
    asm volatile(
        "mma.sync.aligned.m16n8k16.row.col.f32.bf16.bf16.f32 "
        "{%0,%1,%2,%3}, {%4,%5,%6,%7}, {%8,%9}, {%0,%1,%2,%3};"
        : "+f"(c[0]), "+f"(c[1]), "+f"(c[2]), "+f"(c[3])
        : "r"(a[0]), "r"(a[1]), "r"(a[2]), "r"(a[3]), "r"(b0), "r"(b1));
}
__device__ __forceinline__ void mma_h(float* c, const uint32_t* a,
                                      uint32_t b0, uint32_t b1) {
    asm volatile(
        "mma.sync.aligned.m16n8k16.row.col.f32.f16.f16.f32 "
        "{%0,%1,%2,%3}, {%4,%5,%6,%7}, {%8,%9}, {%0,%1,%2,%3};"
        : "+f"(c[0]), "+f"(c[1]), "+f"(c[2]), "+f"(c[3])
        : "r"(a[0]), "r"(a[1]), "r"(a[2]), "r"(a[3]), "r"(b0), "r"(b1));
}
__device__ __forceinline__ void cpa16(uint32_t dst, const void* src) {
    asm volatile("cp.async.ca.shared.global [%0], [%1], 16;"
        :: "r"(dst), "l"(src) : "memory");
}
#define CPA_COMMIT() asm volatile("cp.async.commit_group;" ::: "memory")
#define CPA_WAIT1()  asm volatile("cp.async.wait_group 1;"  ::: "memory")
#define CPA_WAIT0()  asm volatile("cp.async.wait_group 0;"  ::: "memory")

__device__ __forceinline__ void split_store2(
    __nv_bfloat16* H, __nv_bfloat16* L, size_t off, float a, float b)
{
    __nv_bfloat16 ha = __float2bfloat16(a), hb = __float2bfloat16(b);
    __nv_bfloat162 hv, lv;
    hv.x = ha; hv.y = hb;
    lv.x = __float2bfloat16(a - __bfloat162float(ha));
    lv.y = __float2bfloat16(b - __bfloat162float(hb));
    *(__nv_bfloat162*)(H + off) = hv;
    *(__nv_bfloat162*)(L + off) = lv;
}
__device__ __forceinline__ void split_store4(
    __nv_bfloat16* H, __nv_bfloat16* L, size_t off,
    float a, float b, float c, float d)
{
    split_store2(H, L, off,     a, b);
    split_store2(H, L, off + 2, c, d);
}

// ---------------- weight prep ----------------
__global__ void __launch_bounds__(256) split_kernel(
    const float* __restrict__ w, __nv_bfloat16* __restrict__ h,
    __nv_bfloat16* __restrict__ l, int n4)
{
    int i = blockIdx.x * 256 + threadIdx.x;
    if (i >= n4) return;
    float4 v = ((const float4*)w)[i];
    split_store4(h, l, (size_t)i * 4, v.x, v.y, v.z, v.w);
}
__global__ void __launch_bounds__(256) hconv_kernel(
    const float* __restrict__ w, __half* __restrict__ o, int n4)
{
    int i = blockIdx.x * 256 + threadIdx.x;
    if (i >= n4) return;
    float4 v = ((const float4*)w)[i];
    *(__half2*)(o + (size_t)i * 4)     = __floats2half2_rn(v.x, v.y);
    *(__half2*)(o + (size_t)i * 4 + 2) = __floats2half2_rn(v.z, v.w);
}

// ---------------- K1: rmsnorm1 + rel-pos embedding -> bf16 hi/lo ------------
__global__ void __launch_bounds__(256) norm_pe_kernel(
    const float* __restrict__ x, const float* __restrict__ pos,
    const float* __restrict__ nw, const float* __restrict__ pew,
    const float* __restrict__ peb,
    __nv_bfloat16* __restrict__ oh, __nv_bfloat16* __restrict__ ol)
{
    __shared__ float s_pe[768], s_peb[256], s_nw[256], s_pos[384], s_mean[3];
    const int ball = blockIdx.x, tid = threadIdx.x;
    for (int i = tid; i < 768; i += 256) s_pe[i] = pew[i];
    s_peb[tid] = peb[tid];
    s_nw[tid]  = nw[tid];
    for (int i = tid; i < 384; i += 256) s_pos[i] = pos[(size_t)ball * 384 + i];
    __syncthreads();
    if (tid < 3) {
        float s = 0.f;
        for (int t = 0; t < 128; t++) s += s_pos[t * 3 + tid];
        s_mean[tid] = s * (1.f / 128.f);
    }
    __syncthreads();

    const int warp = tid >> 5, lane = tid & 31;
    for (int tok = warp; tok < 128; tok += 8) {
        size_t row = (size_t)ball * 128 + tok;
        const float4* xr = (const float4*)(x + row * 256);
        float4 v0 = xr[lane], v1 = xr[lane + 32];
        float ss = v0.x*v0.x + v0.y*v0.y + v0.z*v0.z + v0.w*v0.w
                 + v1.x*v1.x + v1.y*v1.y + v1.z*v1.z + v1.w*v1.w;
        #pragma unroll
        for (int o = 16; o; o >>= 1) ss += __shfl_xor_sync(0xffffffffu, ss, o);
        float sc = rsqrtf(ss * (1.f / 256.f) + 1e-6f);
        float rx = s_pos[tok*3+0] - s_mean[0];
        float ry = s_pos[tok*3+1] - s_mean[1];
        float rz = s_pos[tok*3+2] - s_mean[2];
        float vin[8] = {v0.x,v0.y,v0.z,v0.w,v1.x,v1.y,v1.z,v1.w};
        float vo[8];
        #pragma unroll
        for (int j = 0; j < 8; j++) {
            int d = (j < 4) ? lane*4 + j : 128 + lane*4 + (j-4);
            vo[j] = vin[j] * sc * s_nw[d]
                  + rx * s_pe[d*3] + ry * s_pe[d*3+1] + rz * s_pe[d*3+2] + s_peb[d];
        }
        split_store4(oh, ol, row*256 + lane*4,       vo[0], vo[1], vo[2], vo[3]);
        split_store4(oh, ol, row*256 + 128 + lane*4, vo[4], vo[5], vo[6], vo[7]);
    }
}

// ---------- GEMM A: 3-term bf16 split (qkv only), 2-stage cp.async ----------
__global__ void __launch_bounds__(256) gemm_split3_kernel(
    const __nv_bfloat16* __restrict__ Ah, const __nv_bfloat16* __restrict__ Al,
    const __nv_bfloat16* __restrict__ Bh, const __nv_bfloat16* __restrict__ Bl,
    const float* __restrict__ bias, float* __restrict__ outF, int Nn, int K)
{
    constexpr int OA0 = 0, OA1 = 10240, OB0 = 20480;
    constexpr int BT  = 10240, CS = 40960;
    extern __shared__ char sm[];
    const uint32_t sb = smem_u32(sm);
    const int tid = threadIdx.x, lane = tid & 31, wid = tid >> 5;
    const int wm = wid >> 1, wn = wid & 1;
    const int bn = blockIdx.x * 128, bm = blockIdx.y * 128;

    float acc[2][8][4];
    #pragma unroll
    for (int mi = 0; mi < 2; mi++)
        #pragma unroll
        for (int ni = 0; ni < 8; ni++)
            #pragma unroll
            for (int q = 0; q < 4; q++) acc[mi][ni][q] = 0.f;

    const int NC = K >> 5;
    auto issue = [&](int c) {
        const int k0 = c << 5;
        const uint32_t bb = sb + (c & 1) * CS;
        #pragma unroll
        for (int i = 0; i < 2; i++) {
            int u = tid + i * 256, r = u >> 2, s = (u & 3) * 8;
            uint32_t so = (uint32_t)r * 80 + s * 2;
            cpa16(bb + OA0 + so, Ah + (size_t)(bm + r) * K + k0 + s);
            cpa16(bb + OA1 + so, Al + (size_t)(bm + r) * K + k0 + s);
            size_t go = (size_t)(bn + r) * K + k0 + s;
            cpa16(bb + OB0 +    so, Bh + go);
            cpa16(bb + OB0 + BT + so, Bl + go);
        }
        CPA_COMMIT();
    };

    issue(0);
    for (int c = 0; c < NC; c++) {
        if (c + 1 < NC) { issue(c + 1); CPA_WAIT1(); }
        else            { CPA_WAIT0(); }
        __syncthreads();
        const uint32_t bb = sb + (c & 1) * CS;
        #pragma unroll
        for (int ks = 0; ks < 32; ks += 16) {
            uint32_t ah[2][4], al[2][4];
            const int ar = lane & 15, ac = ks + (lane >> 4) * 8;
            #pragma unroll
            for (int mi = 0; mi < 2; mi++) {
                uint32_t off = (uint32_t)(wm*32 + mi*16 + ar) * 80 + ac * 2;
                ldsm4(ah[mi], bb + OA0 + off);
                ldsm4(al[mi], bb + OA1 + off);
            }
            const int br = (lane & 7) + ((lane & 16) ? 8 : 0);
            const int bc = ks + ((lane & 8) ? 8 : 0);
            uint32_t bh[4][4], bl[4][4];
            #pragma unroll
            for (int np = 0; np < 4; np++) {
                uint32_t off = (uint32_t)(wn*64 + np*16 + br) * 80 + bc * 2;
                ldsm4(bh[np], bb + OB0 + off);
                ldsm4(bl[np], bb + OB0 + BT + off);
            }
            #pragma unroll
            for (int mi = 0; mi < 2; mi++)
                #pragma unroll
                for (int ni = 0; ni < 8; ni++) {
                    int np = ni >> 1, hb = (ni & 1) * 2;
                    mma_bf(acc[mi][ni], ah[mi], bh[np][hb], bh[np][hb+1]);
                    mma_bf(acc[mi][ni], ah[mi], bl[np][hb], bl[np][hb+1]);
                    mma_bf(acc[mi][ni], al[mi], bh[np][hb], bh[np][hb+1]);
                }
        }
        __syncthreads();
    }

    const int rb = bm + wm*32 + (lane >> 2);
    const int cb = bn + wn*64 + (lane & 3)*2;
    #pragma unroll
    for (int mi = 0; mi < 2; mi++)
        #pragma unroll
        for (int ni = 0; ni < 8; ni++) {
            const int col = cb + ni*8;
            float bx = __ldg(&bias[col]), by = __ldg(&bias[col+1]);
            #pragma unroll
            for (int hr = 0; hr < 2; hr++) {
                size_t o = (size_t)(rb + mi*16 + hr*8) * Nn + col;
                *(float2*)&outF[o] = make_float2(acc[mi][ni][hr*2] + bx,
                                                 acc[mi][ni][hr*2+1] + by);
            }
        }
}

// ---------- GEMM B: single-pass fp16 (proj / w3 / mlp-gate) -----------------
template<bool RES, bool GATE>
__global__ void __launch_bounds__(256) gemm_h_kernel(
    const __half* __restrict__ A,  const __half* __restrict__ B1,
    const __half* __restrict__ B2, const float* __restrict__ bias,
    const float* __restrict__ bias2, const float* __restrict__ res,
    float* __restrict__ outF, __half* __restrict__ outG, int Nn, int K)
{
    constexpr int BN  = GATE ? 64 : 128;
    constexpr int NPW = BN / 32, NI = BN / 16;
    constexpr int OA = 0, OB = 10240;
    constexpr int BT = BN * 80;
    constexpr int CS = 20480;
    extern __shared__ char sm[];
    const uint32_t sb = smem_u32(sm);
    const int tid = threadIdx.x, lane = tid & 31, wid = tid >> 5;
    const int wm = wid >> 1, wn = wid & 1;
    const int bn = blockIdx.x * BN, bm = blockIdx.y * 128;

    float acc [2][NI][4];
    float accV[2][NI][4];
    #pragma unroll
    for (int mi = 0; mi < 2; mi++)
        #pragma unroll
        for (int ni = 0; ni < NI; ni++)
            #pragma unroll
            for (int q = 0; q < 4; q++) {
                acc[mi][ni][q] = 0.f;
                if (GATE) accV[mi][ni][q] = 0.f;
            }

    const int NC = K >> 5;
    auto issue = [&](int c) {
        const int k0 = c << 5;
        const uint32_t bb = sb + (c & 1) * CS;
        #pragma unroll
        for (int i = 0; i < 2; i++) {
            int u = tid + i * 256, r = u >> 2, s = (u & 3) * 8;
            cpa16(bb + OA + (uint32_t)r * 80 + s * 2,
                  A + (size_t)(bm + r) * K + k0 + s);
        }
        if (GATE) {
            int r = tid >> 2, s = (tid & 3) * 8;
            uint32_t so = (uint32_t)r * 80 + s * 2;
            size_t go = (size_t)(bn + r) * K + k0 + s;
            cpa16(bb + OB +    so, B1 + go);
            cpa16(bb + OB + BT + so, B2 + go);
        } else {
            #pragma unroll
            for (int i = 0; i < 2; i++) {
                int u = tid + i * 256, r = u >> 2, s = (u & 3) * 8;
                cpa16(bb + OB + (uint32_t)r * 80 + s * 2,
                      B1 + (size_t)(bn + r) * K + k0 + s);
            }
        }
        CPA_COMMIT();
    };

    issue(0);
    for (int c = 0; c < NC; c++) {
        if (c + 1 < NC) { issue(c + 1); CPA_WAIT1(); }
        else            { CPA_WAIT0(); }
        __syncthreads();
        const uint32_t bb = sb + (c & 1) * CS;
        #pragma unroll
        for (int ks = 0; ks < 32; ks += 16) {
            uint32_t ah[2][4];
            const int ar = lane & 15, ac = ks + (lane >> 4) * 8;
            #pragma unroll
            for (int mi = 0; mi < 2; mi++)
                ldsm4(ah[mi], bb + OA + (uint32_t)(wm*32 + mi*16 + ar) * 80 + ac * 2);
            const int br = (lane & 7) + ((lane & 16) ? 8 : 0);
            const int bc = ks + ((lane & 8) ? 8 : 0);
            uint32_t bh[NPW][4], b2[NPW][4];
            #pragma unroll
            for (int np = 0; np < NPW; np++) {
                uint32_t off = (uint32_t)(wn*(BN/2) + np*16 + br) * 80 + bc * 2;
                ldsm4(bh[np], bb + OB + off);
                if (GATE) ldsm4(b2[np], bb + OB + BT + off);
            }
            #pragma unroll
            for (int mi = 0; mi < 2; mi++)
                #pragma unroll
                for (int ni = 0; ni < NI; ni++) {
                    int np = ni >> 1, hb = (ni & 1) * 2;
                    mma_h(acc[mi][ni], ah[mi], bh[np][hb], bh[np][hb+1]);
                    if (GATE) mma_h(accV[mi][ni], ah[mi], b2[np][hb], b2[np][hb+1]);
                }
        }
        __syncthreads();
    }

    const int rb = bm + wm*32 + (lane >> 2);
    const int cb = bn + wn*(BN/2) + (lane & 3)*2;
    #pragma unroll
    for (int mi = 0; mi < 2; mi++)
        #pragma unroll
        for (int ni = 0; ni < NI; ni++) {
            const int col = cb + ni*8;
            if (GATE) {
                #pragma unroll
                for (int hr = 0; hr < 2; hr++) {
                    size_t o = (size_t)(rb + mi*16 + hr*8) * 1024 + col;
                    float g0 = acc [mi][ni][hr*2]   + __ldg(&bias [col]);
                    float g1 = acc [mi][ni][hr*2+1] + __ldg(&bias [col+1]);
                    float v0 = accV[mi][ni][hr*2]   + __ldg(&bias2[col]);
                    float v1 = accV[mi][ni][hr*2+1] + __ldg(&bias2[col+1]);
                    float r0 = (g0 / (1.f + __expf(-g0))) * v0;
                    float r1 = (g1 / (1.f + __expf(-g1))) * v1;
                    *(__half2*)&outG[o] = __floats2half2_rn(r0, r1);
                }
            } else {
                float bx = __ldg(&bias[col]), by = __ldg(&bias[col+1]);
                #pragma unroll
                for (int hr = 0; hr < 2; hr++) {
                    size_t o = (size_t)(rb + mi*16 + hr*8) * Nn + col;
                    float2 v = make_float2(acc[mi][ni][hr*2] + bx,
                                           acc[mi][ni][hr*2+1] + by);
                    if (RES) {
                        float2 rr = *(const float2*)&res[o];
                        v.x += rr.x; v.y += rr.y;
                    }
                    *(float2*)&outF[o] = v;
                }
            }
        }
}

// ---------------- K3: attention, block per (ball, head), 256 threads --------
// 8 warps x 16 queries; prob staged in fp16 -> smem 74752 B -> 3 blocks/SM.
__global__ void __launch_bounds__(256) attn_kernel(
    const float* __restrict__ qkv, const float* __restrict__ pos,
    const float* __restrict__ sigma, __half* __restrict__ oh)
{
    extern __shared__ float smf[];
    float*  qsm  = smf;                       // [128][36]
    float*  ksm  = qsm + 4608;
    float*  vsm  = ksm + 4608;
    float*  psm  = smf + 13824;               // [128][4]
    __half* prob = (__half*)(smf + 14336);    // 8 warps x [8][136] fp16

    const int ball = blockIdx.x, h = blockIdx.y;
    const int tid = threadIdx.x;
    const size_t base = (size_t)ball * 128 * 768 + (size_t)h * 96;

    for (int idx = tid; idx < 128 * 96; idx += 256) {
        int tok = idx / 96, c = idx - tok * 96;
        int e = c / 3, wch = c - e * 3;
        float v = qkv[base + (size_t)tok * 768 + c];
        if (wch == 0)      qsm[tok * 36 + e] = v;
        else if (wch == 1) ksm[tok * 36 + e] = v;
        else               vsm[tok * 36 + e] = v;
    }
    for (int idx = tid; idx < 384; idx += 256) {
        int tok = idx / 3, c = idx - tok * 3;
        psm[tok * 4 + c] = pos[(size_t)ball * 384 + idx];
    }
    __syncthreads();

    const float sig = sigma[h];
    const float inv = 0.17677669529663687f;   // 1/sqrt(32)
    const int warp = tid >> 5, lane = tid & 31;
    __half* ph = prob + warp * 1088;          // 8*136
    const int qbase = warp * 16;

    float pkx[4], pky[4], pkz[4];
    #pragma unroll
    for (int t = 0; t < 4; t++) {
        int kk = lane * 4 + t;
        pkx[t] = psm[kk*4]; pky[t] = psm[kk*4+1]; pkz[t] = psm[kk*4+2];
    }

    for (int qc = 0; qc < 2; qc++) {
        const int qs = qbase + qc * 8;

        float acc[8][4];
        #pragma unroll
        for (int j = 0; j < 8; j++)
            #pragma unroll
            for (int t = 0; t < 4; t++) acc[j][t] = 0.f;

        #pragma unroll
        for (int e4 = 0; e4 < 8; e4++) {
            float4 kv[4];
            #pragma unroll
            for (int t = 0; t < 4; t++)
                kv[t] = *(const float4*)&ksm[(lane * 4 + t) * 36 + e4 * 4];
            #pragma unroll
            for (int j = 0; j < 8; j++) {
                float4 qv = *(const float4*)&qsm[(qs + j) * 36 + e4 * 4];
                #pragma unroll
                for (int t = 0; t < 4; t++)
                    acc[j][t] += qv.x*kv[t].x + qv.y*kv[t].y + qv.z*kv[t].z + qv.w*kv[t].w;
            }
        }

        #pragma unroll
        for (int j = 0; j < 8; j++) {
            float px = psm[(qs+j)*4], py = psm[(qs+j)*4+1], pz = psm[(qs+j)*4+2];
            float s[4];
            #pragma unroll
            for (int t = 0; t < 4; t++) {
                float dx = px - pkx[t], dy = py - pky[t], dz = pz - pkz[t];
                float dd = sqrtf(dx*dx + dy*dy + dz*dz);
                s[t] = acc[j][t] * inv + sig * dd;
            }
            float m = fmaxf(fmaxf(s[0], s[1]), fmaxf(s[2], s[3]));
            #pragma unroll
            for (int o = 16; o; o >>= 1) m = fmaxf(m, __shfl_xor_sync(0xffffffffu, m, o));
            float e0 = __expf(s[0]-m), e1 = __expf(s[1]-m);
            float e2 = __expf(s[2]-m), e3 = __expf(s[3]-m);
            float sum = e0 + e1 + e2 + e3;
            #pragma unroll
            for (int o = 16; o; o >>= 1) sum += __shfl_xor_sync(0xffffffffu, sum, o);
            float r = 1.f / sum;
            *(__half2*)(ph + j*136 + lane*4)     = __floats2half2_rn(e0*r, e1*r);
            *(__half2*)(ph + j*136 + lane*4 + 2) = __floats2half2_rn(e2*r, e3*r);
        }
        __syncwarp();

        float av[8] = {0,0,0,0,0,0,0,0};
        #pragma unroll 4
        for (int k4 = 0; k4 < 32; k4++) {
            float vv0 = vsm[(k4*4+0)*36 + lane];
            float vv1 = vsm[(k4*4+1)*36 + lane];
            float vv2 = vsm[(k4*4+2)*36 + lane];
            float vv3 = vsm[(k4*4+3)*36 + lane];
            #pragma unroll
            for (int j = 0; j < 8; j++) {
                float2 p01 = __half22float2(*(const __half2*)(ph + j*136 + k4*4));
                float2 p23 = __half22float2(*(const __half2*)(ph + j*136 + k4*4 + 2));
                av[j] += p01.x*vv0 + p01.y*vv1 + p23.x*vv2 + p23.y*vv3;
            }
        }
        #pragma unroll
        for (int j = 0; j < 8; j++) {
            size_t o = ((size_t)ball * 128 + qs + j) * 256 + h * 32 + lane;
            oh[o] = __float2half(av[j]);
        }
        __syncwarp();
    }
}

// ---------------- K5: rmsnorm -> fp16 ----------------
__global__ void __launch_bounds__(256) rmsnorm_kernel(
    const float* __restrict__ x, const float* __restrict__ w,
    __half* __restrict__ oh)
{
    const int warp = threadIdx.x >> 5, lane = threadIdx.x & 31;
    size_t row = (size_t)blockIdx.x * 8 + warp;
    const float4* xr = (const float4*)(x + row * 256);
    float4 v0 = xr[lane], v1 = xr[lane + 32];
    float ss = v0.x*v0.x + v0.y*v0.y + v0.z*v0.z + v0.w*v0.w
             + v1.x*v1.x + v1.y*v1.y + v1.z*v1.z + v1.w*v1.w;
    #pragma unroll
    for (int o = 16; o; o >>= 1) ss += __shfl_xor_sync(0xffffffffu, ss, o);
    float sc = rsqrtf(ss * (1.f / 256.f) + 1e-6f);
    const float4* w4 = (const float4*)w;
    float4 w0 = w4[lane], w1 = w4[lane + 32];
    size_t o0 = row*256 + lane*4, o1 = row*256 + 128 + lane*4;
    *(__half2*)(oh + o0)     = __floats2half2_rn(v0.x*sc*w0.x, v0.y*sc*w0.y);
    *(__half2*)(oh + o0 + 2) = __floats2half2_rn(v0.z*sc*w0.z, v0.w*sc*w0.w);
    *(__half2*)(oh + o1)     = __floats2half2_rn(v1.x*sc*w1.x, v1.y*sc*w1.y);
    *(__half2*)(oh + o1 + 2) = __floats2half2_rn(v1.z*sc*w1.z, v1.w*sc*w1.w);
}

// ---------------------------------------------------------------------------
extern "C" void kernel_launch(void* const* d_in, const int* in_sizes, int n_in,
                              void* d_out, int out_size)
{
    const float* x      = (const float*)d_in[0];
    const float* pos    = (const float*)d_in[1];
    const float* qkv_w  = (const float*)d_in[3];
    const float* qkv_b  = (const float*)d_in[4];
    const float* proj_w = (const float*)d_in[5];
    const float* proj_b = (const float*)d_in[6];
    const float* pe_w   = (const float*)d_in[7];
    const float* pe_b   = (const float*)d_in[8];
    const float* sigma  = (const float*)d_in[9];
    const float* n1w    = (const float*)d_in[10];
    const float* n2w    = (const float*)d_in[11];
    const float* w1w    = (const float*)d_in[12];
    const float* w1b    = (const float*)d_in[13];
    const float* w2w    = (const float*)d_in[14];
    const float* w2b    = (const float*)d_in[15];
    const float* w3w    = (const float*)d_in[16];
    const float* w3b    = (const float*)d_in[17];
    float* out = (float*)d_out;

    float *p_qkv, *p_x2;
    __nv_bfloat16 *p_hh, *p_hl, *p_wqh, *p_wql;
    __half *p_a16, *p_h16, *p_g16, *p_w16;
    cudaGetSymbolAddress((void**)&p_qkv, g_qkv);
    cudaGetSymbolAddress((void**)&p_x2,  g_x2);
    cudaGetSymbolAddress((void**)&p_hh,  g_hh);
    cudaGetSymbolAddress((void**)&p_hl,  g_hl);
    cudaGetSymbolAddress((void**)&p_wqh, g_wqh);
    cudaGetSymbolAddress((void**)&p_wql, g_wql);
    cudaGetSymbolAddress((void**)&p_a16, g_a16);
    cudaGetSymbolAddress((void**)&p_h16, g_h16);
    cudaGetSymbolAddress((void**)&p_g16, g_g16);
    cudaGetSymbolAddress((void**)&p_w16, g_w16);

    const int O_PROJ = 0, O_W1 = 65536, O_W2 = 327680, O_W3 = 589824;

    const int ATTN_SMEM = 14336 * 4 + 8 * 1088 * 2;   // 74752 B -> 3 blocks/SM
    cudaFuncSetAttribute(attn_kernel,
                         cudaFuncAttributeMaxDynamicSharedMemorySize, ATTN_SMEM);
    const int GSM  = 81920;   // split3: 2 x 40960
    const int GSMH = 40960;   // fp16:  2 x 20480
    cudaFuncSetAttribute(gemm_split3_kernel, cudaFuncAttributeMaxDynamicSharedMemorySize, GSM);
    cudaFuncSetAttribute(gemm_h_kernel<true,false>,  cudaFuncAttributeMaxDynamicSharedMemorySize, GSMH);
    cudaFuncSetAttribute(gemm_h_kernel<false,true>,  cudaFuncAttributeMaxDynamicSharedMemorySize, GSMH);

    // 0) weight prep
    split_kernel<<<(196608/4+255)/256, 256>>>(qkv_w, p_wqh, p_wql, 196608/4);
    hconv_kernel<<<( 65536/4+255)/256, 256>>>(proj_w, p_w16+O_PROJ,  65536/4);
    hconv_kernel<<<(262144/4+255)/256, 256>>>(w1w,    p_w16+O_W1,   262144/4);
    hconv_kernel<<<(262144/4+255)/256, 256>>>(w2w,    p_w16+O_W2,   262144/4);
    hconv_kernel<<<(262144/4+255)/256, 256>>>(w3w,    p_w16+O_W3,   262144/4);

    // 1) h = rmsnorm1(x) + pe   (bf16 hi/lo)
    norm_pe_kernel<<<NBALLS, 256>>>(x, pos, n1w, pe_w, pe_b, p_hh, p_hl);

    // 2) qkv = h @ qkv_w^T + b   (3-term bf16 split, fp32 out, stride 768)
    gemm_split3_kernel<<<dim3(6, NTOK/128), 256, GSM>>>(
        p_hh, p_hl, p_wqh, p_wql, qkv_b, p_qkv, 768, 256);

    // 3) att = ball attention    (fp16 out)
    attn_kernel<<<dim3(NBALLS, 8), 256, ATTN_SMEM>>>(p_qkv, pos, sigma, p_a16);

    // 4) x2 = att @ proj^T + b + x   (fp16 single-pass)
    gemm_h_kernel<true,false><<<dim3(2, NTOK/128), 256, GSMH>>>(
        p_a16, p_w16+O_PROJ, nullptr, proj_b, nullptr, x, p_x2, nullptr, 256, 256);

    // 5) h = rmsnorm2(x2)        (fp16)
    rmsnorm_kernel<<<NTOK/8, 256>>>(p_x2, n2w, p_h16);

    // 6) g = silu(h@w1^T+b1)*(h@w2^T+b2)   (fp16, stride 1024)
    gemm_h_kernel<false,true><<<dim3(16, NTOK/128), 256, GSMH>>>(
        p_h16, p_w16+O_W1, p_w16+O_W2, w1b, w2b, nullptr, nullptr, p_g16, 1024, 256);

    // 7) out = g @ w3^T + b3 + x2   (fp16 single-pass)
    gemm_h_kernel<true,false><<<dim3(2, NTOK/128), 256, GSMH>>>(
        p_g16, p_w16+O_W3, nullptr, w3b, nullptr, p_x2, out, nullptr, 256, 1024);
}